// round 16
// baseline (speedup 1.0000x reference)
#include <cuda_runtime.h>
#include <cuda_fp16.h>
#include <cstdint>

// ---------------------------------------------------------------------------
// Fastformer — fp16 SS mma.sync GEMMs, BK=64 chunks (half the barrier count),
// 3-stage pipeline, 2 CTA/SM. Logits kernels: 8 rows/warp on fp16.
// ---------------------------------------------------------------------------

#define Bc 8
#define Sc 2048
#define Dc 1024
#define Hc 16
#define DHc 64
#define Mc (Bc * Sc)   // 16384

__device__ float  g_Q[Mc * Dc];
__device__ float  g_K[Mc * Dc];
__device__ __half g_Qh[Mc * Dc];        // h(Q) from gemm_qk epilogue
__device__ __half g_Kh[Mc * Dc];        // h(K) from gemm_qk epilogue
__device__ __half g_Qsh[Mc * Dc];       // fp16 inputs; reused by scaleh
__device__ __half g_Ksh[Mc * Dc];
__device__ __half g_WQt[Dc * Dc];       // [n][k] transposed fp16 weights
__device__ __half g_WKt[Dc * Dc];
__device__ __half g_WPt[Dc * Dc];
__device__ __half g_Wah[Dc * Hc];       // fp16 Wa (row-major [d][e])
__device__ __half g_Wbh[Dc * Hc];
__device__ float  g_logA[Bc * Hc * Sc];
__device__ float  g_logB[Bc * Hc * Sc];
__device__ float  g_qg[Bc * Hc * DHc];
__device__ float  g_kg[Bc * Dc];

// ===========================================================================
__device__ __forceinline__ uint32_t cvta_smem(const void* p) {
    uint32_t a;
    asm("{ .reg .u64 t; cvta.to.shared.u64 t, %1; cvt.u32.u64 %0, t; }" : "=r"(a) : "l"(p));
    return a;
}
__device__ __forceinline__ void cp16(uint32_t s, const void* g) {
    asm volatile("cp.async.cg.shared.global [%0], [%1], 16;" :: "r"(s), "l"(g));
}
__device__ __forceinline__ void cp_commit() {
    asm volatile("cp.async.commit_group;" ::: "memory");
}
template <int N>
__device__ __forceinline__ void cp_wait() {
    asm volatile("cp.async.wait_group %0;" :: "n"(N) : "memory");
}
__device__ __forceinline__ void ldmx4(uint32_t& r0, uint32_t& r1, uint32_t& r2, uint32_t& r3,
                                      uint32_t addr) {
    asm volatile("ldmatrix.sync.aligned.m8n8.x4.shared.b16 {%0,%1,%2,%3}, [%4];"
                 : "=r"(r0), "=r"(r1), "=r"(r2), "=r"(r3) : "r"(addr));
}
__device__ __forceinline__ void mma_f16(float& c0, float& c1, float& c2, float& c3,
                                        uint32_t a0, uint32_t a1, uint32_t a2, uint32_t a3,
                                        uint32_t b0, uint32_t b1) {
    asm volatile(
        "mma.sync.aligned.m16n8k16.row.col.f32.f16.f16.f32 "
        "{%0,%1,%2,%3}, {%4,%5,%6,%7}, {%8,%9}, {%0,%1,%2,%3};"
        : "+f"(c0), "+f"(c1), "+f"(c2), "+f"(c3)
        : "r"(a0), "r"(a1), "r"(a2), "r"(a3), "r"(b0), "r"(b1));
}
__device__ __forceinline__ uint32_t pack_h2(float x, float y) {
    __half2 h = __floats2half2_rn(x, y);
    return *reinterpret_cast<uint32_t*>(&h);
}

// ===========================================================================
// GEMM: BM=BN=128, BK=64, 128 thr (2x2 warps, 64x64 tiles), fp16 m16n8k16,
// 3-stage cp.async, ONE barrier per 64-wide chunk, 2 CTAs/SM.
// RES: epilogue += resid.  WH: also store h(C) to Ch.
// RSTRIDE=144B (128B data + 16B pad): 16B-aligned, conflict-free ldmatrix
// (144*lr mod 128 = 16*lr covers all eight banks).
// ===========================================================================
#define RSTRIDE 144
#define TILEB (128 * RSTRIDE)       // 18432
#define STGB (2 * TILEB)            // 36864
#define NSTG 3
#define GSMEM (NSTG * STGB)         // 110592
#define NCH (Dc / 64)               // 16

template <int RES, int WH>
__device__ __forceinline__ void gemm_body(
    const __half* __restrict__ A, const __half* __restrict__ Bt,
    float* __restrict__ C, __half* __restrict__ Ch,
    const float* __restrict__ resid)
{
    extern __shared__ char smem[];
    const uint32_t sb = cvta_smem(smem);
    const int tid  = threadIdx.x;
    const int wid  = tid >> 5, lane = tid & 31;
    const int g    = lane >> 2, t = lane & 3;
    const int wm   = wid >> 1, wn = wid & 1;
    const int crow = blockIdx.y * 128, ccol = blockIdx.x * 128;

    // loaders: 8 thr/row (16B fp16 each), 16 rows/pass, 8 passes
    const int lrow = tid >> 3, lseg = tid & 7;
    const __half* Ag = A  + (size_t)(crow + lrow) * Dc + lseg * 8;
    const __half* Bg = Bt + (size_t)(ccol + lrow) * Dc + lseg * 8;
    const uint32_t sA = (uint32_t)(lrow * RSTRIDE + lseg * 16);
    const uint32_t sB = (uint32_t)(TILEB + lrow * RSTRIDE + lseg * 16);

    // ldmatrix per-lane offsets
    const int ltile = lane >> 3, lr = lane & 7;
    uint32_t offA[4], offB[4];
#pragma unroll
    for (int im = 0; im < 4; im++)
        offA[im] = (uint32_t)((wm * 64 + im * 16 + (ltile & 1) * 8 + lr) * RSTRIDE
                              + (ltile >> 1) * 16);
#pragma unroll
    for (int j = 0; j < 4; j++)
        offB[j] = (uint32_t)(TILEB + (wn * 64 + j * 16 + (ltile >> 1) * 8 + lr) * RSTRIDE
                             + (ltile & 1) * 16);

    float acc[4][8][4];
#pragma unroll
    for (int i = 0; i < 4; i++)
#pragma unroll
        for (int j = 0; j < 8; j++)
#pragma unroll
            for (int k = 0; k < 4; k++) acc[i][j][k] = 0.f;

    auto issue = [&](int c) {
        uint32_t base = sb + (uint32_t)(c % NSTG) * STGB;
        const __half* ag = Ag + c * 64;
        const __half* bg = Bg + c * 64;
#pragma unroll
        for (int p = 0; p < 8; p++) {
            cp16(base + sA + p * 16 * RSTRIDE, ag + (size_t)p * 16 * Dc);
            cp16(base + sB + p * 16 * RSTRIDE, bg + (size_t)p * 16 * Dc);
        }
        cp_commit();
    };

    issue(0); issue(1);

    for (int c = 0; c < NCH; c++) {
        if (c + 1 < NCH) cp_wait<1>(); else cp_wait<0>();
        __syncthreads();                 // stage c visible; slot (c-1)%3 drained
        if (c + 2 < NCH) issue(c + 2);

        const uint32_t base = sb + (uint32_t)(c % NSTG) * STGB;

#pragma unroll
        for (int kk = 0; kk < 4; kk++) {     // 16 k-values per kk, 64 total
            uint32_t a[4][4], b[8][2];
#pragma unroll
            for (int im = 0; im < 4; im++)
                ldmx4(a[im][0], a[im][1], a[im][2], a[im][3],
                      base + offA[im] + kk * 32);
#pragma unroll
            for (int j = 0; j < 4; j++) {
                uint32_t r0, r1, r2, r3;
                ldmx4(r0, r1, r2, r3, base + offB[j] + kk * 32);
                b[2 * j][0] = r0;     b[2 * j][1] = r1;
                b[2 * j + 1][0] = r2; b[2 * j + 1][1] = r3;
            }
#pragma unroll
            for (int im = 0; im < 4; im++)
#pragma unroll
                for (int in = 0; in < 8; in++)
                    mma_f16(acc[im][in][0], acc[im][in][1], acc[im][in][2], acc[im][in][3],
                            a[im][0], a[im][1], a[im][2], a[im][3],
                            b[in][0], b[in][1]);
        }
    }
    __syncthreads();

    // epilogue (fragment rows g, g+8; cols 2t, 2t+1)
#pragma unroll
    for (int im = 0; im < 4; im++) {
#pragma unroll
        for (int in = 0; in < 8; in++) {
            const int r0 = crow + wm * 64 + im * 16 + g;
            const int cc = ccol + wn * 64 + in * 8 + 2 * t;
            float2 v0 = make_float2(acc[im][in][0], acc[im][in][1]);
            float2 v1 = make_float2(acc[im][in][2], acc[im][in][3]);
            if (RES) {
                float2 q0 = *(const float2*)(resid + (size_t)r0 * Dc + cc);
                float2 q1 = *(const float2*)(resid + (size_t)(r0 + 8) * Dc + cc);
                v0.x += q0.x; v0.y += q0.y; v1.x += q1.x; v1.y += q1.y;
            }
            *(float2*)(C + (size_t)r0 * Dc + cc) = v0;
            *(float2*)(C + (size_t)(r0 + 8) * Dc + cc) = v1;
            if (WH) {
                *(uint32_t*)(Ch + (size_t)r0 * Dc + cc) = pack_h2(v0.x, v0.y);
                *(uint32_t*)(Ch + (size_t)(r0 + 8) * Dc + cc) = pack_h2(v1.x, v1.y);
            }
        }
    }
}

__global__ __launch_bounds__(128, 2)
void gemm_qk(const __half* __restrict__ Aq, const __half* __restrict__ Ak,
             const __half* __restrict__ Bq, const __half* __restrict__ Bk,
             float* __restrict__ Cq, float* __restrict__ Ck,
             __half* __restrict__ Qh, __half* __restrict__ Kh)
{
    if (blockIdx.z == 0) gemm_body<0, 1>(Aq, Bq, Cq, Qh, nullptr);
    else                 gemm_body<0, 1>(Ak, Bk, Ck, Kh, nullptr);
}

__global__ __launch_bounds__(128, 2)
void gemm_out(const __half* __restrict__ A, const __half* __restrict__ Bt,
              float* __restrict__ C, const float* __restrict__ resid)
{
    gemm_body<1, 0>(A, Bt, C, nullptr, resid);
}

// ===========================================================================
// weight prep: z<3 -> transpose+fp16; z==3 -> fp16 copies of Wa/Wb
// ===========================================================================
__global__ void tcvt_k(const float* __restrict__ W0, const float* __restrict__ W1,
                       const float* __restrict__ W2,
                       __half* __restrict__ T0, __half* __restrict__ T1,
                       __half* __restrict__ T2,
                       const float* __restrict__ Wa, const float* __restrict__ Wb,
                       __half* __restrict__ Tah, __half* __restrict__ Tbh)
{
    int tx = threadIdx.x, ty = threadIdx.y;
    if (blockIdx.z == 3) {
        if (blockIdx.x > 1) return;
        const float* S = blockIdx.x ? Wb : Wa;
        __half* D      = blockIdx.x ? Tbh : Tah;
        int k0 = blockIdx.y * 32;
        if (tx < 16) {
#pragma unroll
            for (int i = 0; i < 32; i += 8)
                D[(k0 + ty + i) * Hc + tx] = __float2half_rn(S[(k0 + ty + i) * Hc + tx]);
        }
        return;
    }
    const float* W = (blockIdx.z == 0) ? W0 : (blockIdx.z == 1) ? W1 : W2;
    __half* Wt     = (blockIdx.z == 0) ? T0 : (blockIdx.z == 1) ? T1 : T2;
    __shared__ float tbuf[32][33];
    int n0 = blockIdx.x * 32, k0 = blockIdx.y * 32;
#pragma unroll
    for (int i = 0; i < 32; i += 8) tbuf[ty + i][tx] = W[(size_t)(k0 + ty + i) * Dc + n0 + tx];
    __syncthreads();
#pragma unroll
    for (int i = 0; i < 32; i += 8)
        Wt[(size_t)(n0 + ty + i) * Dc + k0 + tx] = __float2half_rn(tbuf[tx][ty + i]);
}

// fp32 -> fp16 elementwise
__global__ void cvth_k(const float* __restrict__ in, __half* __restrict__ out, int n4)
{
    int i = blockIdx.x * blockDim.x + threadIdx.x;
    if (i >= n4) return;
    float4 v = ((const float4*)in)[i];
    uint2 o = make_uint2(pack_h2(v.x, v.y), pack_h2(v.z, v.w));
    ((uint2*)out)[i] = o;
}

// g_Qsh[m][k] = half(g_Q[m][k] * kg[b,k])
__global__ void scaleh_k()
{
    int i = blockIdx.x * blockDim.x + threadIdx.x;
    int k4 = i & 255, m = i >> 8, b = m >> 11;
    float4 v = ((const float4*)g_Q)[i];
    float4 s = ((const float4*)g_kg)[b * 256 + k4];
    uint2 o = make_uint2(pack_h2(v.x * s.x, v.y * s.y), pack_h2(v.z * s.z, v.w * s.w));
    ((uint2*)g_Qsh)[i] = o;
}

// ===========================================================================
// logitsA: one warp per 8 rows, fp16 Q + fp16 Wa, fp32 accumulate.
// ===========================================================================
__global__ __launch_bounds__(128)
void logitsA_k()
{
    int gw = (blockIdx.x * blockDim.x + threadIdx.x) >> 5;
    int lane = threadIdx.x & 31;
    int b = gw >> 8;
    int s0 = (gw & 255) * 8;
    const __half* q = g_Qh + ((size_t)gw * 8) * Dc;

    float acc[8][16];
#pragma unroll
    for (int r = 0; r < 8; r++)
#pragma unroll
        for (int e = 0; e < 16; e++) acc[r][e] = 0.f;

    for (int i = 0; i < 4; i++) {
        int d8 = lane + 32 * i;
        uint4 qv[8];
#pragma unroll
        for (int r = 0; r < 8; r++)
            qv[r] = *reinterpret_cast<const uint4*>(q + (size_t)r * Dc + d8 * 8);
        const __half* wa = g_Wah + (size_t)d8 * 8 * Hc;
#pragma unroll
        for (int dd = 0; dd < 8; dd++) {
            uint4 w0 = *reinterpret_cast<const uint4*>(wa + dd * Hc);
            uint4 w1 = *reinterpret_cast<const uint4*>(wa + dd * Hc + 8);
            float we[16];
            {
                const __half2* wp0 = reinterpret_cast<const __half2*>(&w0);
                const __half2* wp1 = reinterpret_cast<const __half2*>(&w1);
#pragma unroll
                for (int p = 0; p < 4; p++) {
                    float2 f0 = __half22float2(wp0[p]);
                    float2 f1 = __half22float2(wp1[p]);
                    we[2 * p] = f0.x;     we[2 * p + 1] = f0.y;
                    we[8 + 2 * p] = f1.x; we[8 + 2 * p + 1] = f1.y;
                }
            }
#pragma unroll
            for (int r = 0; r < 8; r++) {
                const __half* qh = reinterpret_cast<const __half*>(&qv[r]);
                float qf = __half2float(qh[dd]);
#pragma unroll
                for (int e = 0; e < 16; e++) acc[r][e] += qf * we[e];
            }
        }
    }

#pragma unroll
    for (int e = 0; e < 16; e++) {
        float v[8];
#pragma unroll
        for (int r = 0; r < 8; r++) v[r] = acc[r][e];
#pragma unroll
        for (int o = 16; o; o >>= 1)
#pragma unroll
            for (int r = 0; r < 8; r++) v[r] += __shfl_xor_sync(0xffffffffu, v[r], o);
        if (lane == e) {
            float* dst = g_logA + (b * Hc + e) * Sc + s0;
#pragma unroll
            for (int r = 0; r < 8; r++) dst[r] = v[r] * 0.125f;
        }
    }
}

// ===========================================================================
// logitsB: one warp per 8 scrambled rows, fp16 K + fp16 Wb.
// ===========================================================================
__global__ __launch_bounds__(128)
void logitsB_k()
{
    int gw = (blockIdx.x * blockDim.x + threadIdx.x) >> 5;
    int lane = threadIdx.x & 31;
    int b = gw >> 8;
    int spL = (gw & 255) * 8;
    int h0 = spL >> 7;
    int s0 = (spL & 127) << 4;

    const float* qgv = g_qg + (b * Hc + h0) * DHc;
    const __half* Kb = g_Kh + ((size_t)(b * Sc + s0)) * Dc + h0 * DHc;

    float acc[8][16];
#pragma unroll
    for (int r = 0; r < 8; r++)
#pragma unroll
        for (int e = 0; e < 16; e++) acc[r][e] = 0.f;

    for (int i = 0; i < 32; i++) {
        int k = lane + 32 * i;
        int tt = k >> 6, j = k & 63;
        float qv = qgv[j];
        float vr[8];
#pragma unroll
        for (int r = 0; r < 8; r++)
            vr[r] = __half2float(Kb[(size_t)(r * 16 + tt) * Dc + j]) * qv;

        uint4 w0 = *reinterpret_cast<const uint4*>(g_Wbh + (size_t)k * Hc);
        uint4 w1 = *reinterpret_cast<const uint4*>(g_Wbh + (size_t)k * Hc + 8);
        float we[16];
        {
            const __half2* wp0 = reinterpret_cast<const __half2*>(&w0);
            const __half2* wp1 = reinterpret_cast<const __half2*>(&w1);
#pragma unroll
            for (int p = 0; p < 4; p++) {
                float2 f0 = __half22float2(wp0[p]);
                float2 f1 = __half22float2(wp1[p]);
                we[2 * p] = f0.x;     we[2 * p + 1] = f0.y;
                we[8 + 2 * p] = f1.x; we[8 + 2 * p + 1] = f1.y;
            }
        }
#pragma unroll
        for (int r = 0; r < 8; r++)
#pragma unroll
            for (int e = 0; e < 16; e++) acc[r][e] += vr[r] * we[e];
    }

#pragma unroll
    for (int e = 0; e < 16; e++) {
        float v[8];
#pragma unroll
        for (int r = 0; r < 8; r++) v[r] = acc[r][e];
#pragma unroll
        for (int o = 16; o; o >>= 1)
#pragma unroll
            for (int r = 0; r < 8; r++) v[r] += __shfl_xor_sync(0xffffffffu, v[r], o);
        if (lane == e) {
            float* dst = g_logB + (b * Hc + e) * Sc + spL;
#pragma unroll
            for (int r = 0; r < 8; r++) dst[r] = v[r] * 0.125f;
        }
    }
}

// ===========================================================================
__global__ void pool_k(const float* __restrict__ logits, const float* __restrict__ X,
                       const float* __restrict__ qscale, float* __restrict__ out)
{
    int bh = blockIdx.x;
    int b = bh >> 4, h = bh & 15;
    const float* lg = logits + bh * Sc;

    __shared__ float sE[Sc];
    __shared__ float red[16];
    __shared__ float part[8][DHc];

    int tid = threadIdx.x, lane = tid & 31, warp = tid >> 5;

    float mx = -1e30f;
    for (int s = tid; s < Sc; s += 512) mx = fmaxf(mx, lg[s]);
#pragma unroll
    for (int o = 16; o; o >>= 1) mx = fmaxf(mx, __shfl_xor_sync(0xffffffffu, mx, o));
    if (lane == 0) red[warp] = mx;
    __syncthreads();
    mx = red[0];
#pragma unroll
    for (int i = 1; i < 16; i++) mx = fmaxf(mx, red[i]);
    __syncthreads();

    float sum = 0.f;
    for (int s = tid; s < Sc; s += 512) {
        float e = __expf(lg[s] - mx);
        sE[s] = e;
        sum += e;
    }
#pragma unroll
    for (int o = 16; o; o >>= 1) sum += __shfl_xor_sync(0xffffffffu, sum, o);
    if (lane == 0) red[warp] = sum;
    __syncthreads();
    float tot = 0.f;
#pragma unroll
    for (int i = 0; i < 16; i++) tot += red[i];
    float inv = 1.0f / tot;

    int j = tid & 63, gg = tid >> 6;
    const float* Xb = X + ((size_t)b * Sc) * Dc + h * DHc + j;
    float a0 = 0.f, a1 = 0.f, a2 = 0.f, a3 = 0.f;
    for (int s = gg; s < Sc; s += 32) {
        a0 += sE[s]      * Xb[(size_t)s * Dc];
        a1 += sE[s + 8]  * Xb[(size_t)(s + 8)  * Dc];
        a2 += sE[s + 16] * Xb[(size_t)(s + 16) * Dc];
        a3 += sE[s + 24] * Xb[(size_t)(s + 24) * Dc];
    }
    part[gg][j] = (a0 + a1) + (a2 + a3);
    __syncthreads();
    if (gg == 0) {
        float v = 0.f;
#pragma unroll
        for (int i = 0; i < 8; i++) v += part[i][j];
        v *= inv;
        if (qscale) v *= qscale[bh * DHc + j];
        out[bh * DHc + j] = v;
    }
}

// ===========================================================================
extern "C" void kernel_launch(void* const* d_in, const int* in_sizes, int n_in,
                              void* d_out, int out_size)
{
    const float* Qseq = (const float*)d_in[0];
    const float* Kseq = (const float*)d_in[1];
    const float* WQ = (const float*)d_in[3];
    const float* WK = (const float*)d_in[4];
    const float* Wa = (const float*)d_in[5];
    const float* Wb = (const float*)d_in[6];
    const float* WP = (const float*)d_in[7];
    float* out = (float*)d_out;

    float *pQ, *pK, *pLA, *pLB, *pqg, *pkg;
    __half *pQh, *pKh, *pQsh, *pKsh, *pWQ, *pWK, *pWP, *pWah, *pWbh;
    cudaGetSymbolAddress((void**)&pQ,   g_Q);
    cudaGetSymbolAddress((void**)&pK,   g_K);
    cudaGetSymbolAddress((void**)&pQh,  g_Qh);
    cudaGetSymbolAddress((void**)&pKh,  g_Kh);
    cudaGetSymbolAddress((void**)&pQsh, g_Qsh);
    cudaGetSymbolAddress((void**)&pKsh, g_Ksh);
    cudaGetSymbolAddress((void**)&pWQ,  g_WQt);
    cudaGetSymbolAddress((void**)&pWK,  g_WKt);
    cudaGetSymbolAddress((void**)&pWP,  g_WPt);
    cudaGetSymbolAddress((void**)&pWah, g_Wah);
    cudaGetSymbolAddress((void**)&pWbh, g_Wbh);
    cudaGetSymbolAddress((void**)&pLA,  g_logA);
    cudaGetSymbolAddress((void**)&pLB,  g_logB);
    cudaGetSymbolAddress((void**)&pqg,  g_qg);
    cudaGetSymbolAddress((void**)&pkg,  g_kg);

    cudaFuncSetAttribute(gemm_qk,  cudaFuncAttributeMaxDynamicSharedMemorySize, GSMEM);
    cudaFuncSetAttribute(gemm_out, cudaFuncAttributeMaxDynamicSharedMemorySize, GSMEM);

    const int big4 = Mc * Dc / 4;
    dim3 tg(32, 32, 4), tb(32, 8);
    dim3 ggqk(Dc / 128, Mc / 128, 2);
    dim3 gg(Dc / 128, Mc / 128);

    tcvt_k<<<tg, tb>>>(WQ, WK, WP, pWQ, pWK, pWP, Wa, Wb, pWah, pWbh);     // 1
    cvth_k<<<(big4 + 255) / 256, 256>>>(Qseq, pQsh, big4);                 // 2
    cvth_k<<<(big4 + 255) / 256, 256>>>(Kseq, pKsh, big4);                 // 3
    gemm_qk<<<ggqk, 128, GSMEM>>>(pQsh, pKsh, pWQ, pWK, pQ, pK, pQh, pKh); // 4 <- profiled
    logitsA_k<<<Mc / 8 / 4, 128>>>();                                      // 5
    pool_k<<<Bc * Hc, 512>>>(pLA, pQ, nullptr, pqg);                       // 6
    logitsB_k<<<Mc / 8 / 4, 128>>>();                                      // 7
    pool_k<<<Bc * Hc, 512>>>(pLB, pK, pqg, pkg);                           // 8
    scaleh_k<<<big4 / 256, 256>>>();                                       // 9
    gemm_out<<<gg, 128, GSMEM>>>(pQsh, pWP, out, pQ);                      // 10
}